// round 1
// baseline (speedup 1.0000x reference)
#include <cuda_runtime.h>
#include <math.h>

// Problem constants (fixed by the reference)
#define T_LEN 128
#define B_ENV 4096
#define N_TOT (T_LEN * B_ENV)   // 524288
#define HID   128
#define FEAT  96
#define NA    6

// ---------------------------------------------------------------------------
// Scratch (device globals — no runtime allocation allowed)
// ---------------------------------------------------------------------------
__device__ float g_b0[(size_t)N_TOT * 256];   // 512 MB ping
__device__ float g_b1[(size_t)N_TOT * 256];   // 512 MB pong
__device__ float g_feat[(size_t)N_TOT * 96];  // 192 MB concat features
__device__ float g_gx[(size_t)N_TOT * 512];   // 1 GB  precomputed x-gates

__device__ __forceinline__ float sigf(float x) { return 1.f / (1.f + expf(-x)); }

// ---------------------------------------------------------------------------
// Generic tiled SGEMM: C[M,N] = act(A[M,K]*aScale @ B + bias (+bias2))
// BM=128, BN=128, BK=8, 256 threads, 8x8 register tile per thread.
// TRANSB=false: B is [K,N] row-major.  TRANSB=true: B is [N,K] row-major.
// C written at C[row*ldc + coff + col].
// ---------------------------------------------------------------------------
template <bool TRANSB, bool RELU>
__global__ __launch_bounds__(256) void gemm_bias_kernel(
    const float* __restrict__ A, const float* __restrict__ B,
    const float* __restrict__ bias, const float* __restrict__ bias2,
    float* __restrict__ C, int M, int N, int K, float aScale, int ldc, int coff)
{
    __shared__ __align__(16) float As[8][132];
    __shared__ __align__(16) float Bs[8][132];

    const int tid = threadIdx.x;
    const int tr = tid >> 4;        // 0..15
    const int tc = tid & 15;        // 0..15
    const int rowBase = blockIdx.x * 128;
    const int colBase = blockIdx.y * 128;

    float acc[8][8];
#pragma unroll
    for (int i = 0; i < 8; i++)
#pragma unroll
        for (int j = 0; j < 8; j++) acc[i][j] = 0.f;

    for (int k0 = 0; k0 < K; k0 += 8) {
        // Load A tile (128 x 8)
#pragma unroll
        for (int i = tid; i < 1024; i += 256) {
            int m = i >> 3, k = i & 7;
            int gk = k0 + k;
            As[k][m] = (gk < K) ? A[(rowBase + m) * K + gk] * aScale : 0.f;
        }
        // Load B tile (8 x 128)
#pragma unroll
        for (int i = tid; i < 1024; i += 256) {
            int n = i >> 3, k = i & 7;
            int gk = k0 + k;
            int gn = colBase + n;
            float v = 0.f;
            if (gk < K && gn < N)
                v = TRANSB ? B[gn * K + gk] : B[gk * N + gn];
            Bs[k][n] = v;
        }
        __syncthreads();

#pragma unroll
        for (int k = 0; k < 8; k++) {
            float4 a0 = *(const float4*)&As[k][tr * 8];
            float4 a1 = *(const float4*)&As[k][tr * 8 + 4];
            float4 b0 = *(const float4*)&Bs[k][tc * 8];
            float4 b1 = *(const float4*)&Bs[k][tc * 8 + 4];
            float a[8] = {a0.x, a0.y, a0.z, a0.w, a1.x, a1.y, a1.z, a1.w};
            float b[8] = {b0.x, b0.y, b0.z, b0.w, b1.x, b1.y, b1.z, b1.w};
#pragma unroll
            for (int i = 0; i < 8; i++)
#pragma unroll
                for (int j = 0; j < 8; j++) acc[i][j] += a[i] * b[j];
        }
        __syncthreads();
    }

#pragma unroll
    for (int i = 0; i < 8; i++) {
        int row = rowBase + tr * 8 + i;
#pragma unroll
        for (int j = 0; j < 8; j++) {
            int col = colBase + tc * 8 + j;
            if (col < N) {
                float v = acc[i][j] + bias[col];
                if (bias2) v += bias2[col];
                if (RELU) v = fmaxf(v, 0.f);
                C[row * ldc + coff + col] = v;
            }
        }
    }
}

// ---------------------------------------------------------------------------
// Tiny loc/energy encoders -> feats columns [32:64) and [64:96)
// ---------------------------------------------------------------------------
__global__ void smallenc_kernel(const float* __restrict__ loc,
                                const float* __restrict__ eng,
                                const float* __restrict__ Wl,
                                const float* __restrict__ bl,
                                const float* __restrict__ We,
                                const float* __restrict__ be,
                                float* __restrict__ feats)
{
    int idx = blockIdx.x * blockDim.x + threadIdx.x;
    if (idx >= N_TOT * 64) return;
    int n = idx >> 6;
    int j = idx & 63;
    if (j < 32) {
        float v = (loc[n * 2 + 0] * 0.1f) * Wl[j] +
                  (loc[n * 2 + 1] * 0.1f) * Wl[32 + j] + bl[j];
        feats[n * 96 + 32 + j] = v;
    } else {
        int jj = j - 32;
        float v = (eng[n] * (1.f / 200.f)) * We[jj] + be[jj];
        feats[n * 96 + 64 + jj] = v;
    }
}

// ---------------------------------------------------------------------------
// LSTM: one CTA owns LROWS batch rows, loops all T=128 steps locally.
// gates = gx (precomputed x@Wih^T + bih + bhh) + h @ Whh^T.
// Heads fused: writes out[(t*B+b)*7 + {0..6}] directly.
// ---------------------------------------------------------------------------
#define LROWS 16

__global__ __launch_bounds__(512) void lstm_kernel(
    const float* __restrict__ gx, const int* __restrict__ done,
    const float* __restrict__ h0, const float* __restrict__ c0,
    const float* __restrict__ Whh,
    const float* __restrict__ Wa, const float* __restrict__ ba,
    const float* __restrict__ Wc, const float* __restrict__ bc,
    float* __restrict__ out)
{
    __shared__ __align__(16) float h_s[LROWS][HID];   // 8 KB
    __shared__ __align__(16) float c_s[LROWS][HID];   // 8 KB
    __shared__ float gs[LROWS][4 * HID];              // 32 KB

    const int tid = threadIdx.x;      // 512 threads: one per gate column j
    const int r0 = blockIdx.x * LROWS;

    // init h, c from inputs
    for (int e = tid; e < LROWS * HID; e += 512) {
        int r = e >> 7, k = e & 127;
        h_s[r][k] = h0[(r0 + r) * HID + k];
        c_s[r][k] = c0[(r0 + r) * HID + k];
    }
    __syncthreads();

    for (int t = 0; t < T_LEN; t++) {
        // done mask: reset h, c
        for (int e = tid; e < LROWS * HID; e += 512) {
            int r = e >> 7, k = e & 127;
            if (done[t * B_ENV + r0 + r]) { h_s[r][k] = 0.f; c_s[r][k] = 0.f; }
        }
        __syncthreads();

        // gates[r][j] = gx[t, r0+r, j] + sum_k Whh[j,k] * h[r,k]
        {
            const int j = tid;
            float acc[LROWS];
            const float* gxp = gx + ((long long)t * B_ENV + r0) * 512 + j;
#pragma unroll
            for (int r = 0; r < LROWS; r++) acc[r] = gxp[r * 512];

            const float4* wp = (const float4*)(Whh + j * HID);
#pragma unroll 8
            for (int kk = 0; kk < HID / 4; kk++) {
                float4 w = wp[kk];
#pragma unroll
                for (int r = 0; r < LROWS; r++) {
                    float4 h4 = *(const float4*)&h_s[r][kk * 4];
                    acc[r] += w.x * h4.x + w.y * h4.y + w.z * h4.z + w.w * h4.w;
                }
            }
#pragma unroll
            for (int r = 0; r < LROWS; r++) gs[r][j] = acc[r];
        }
        __syncthreads();

        // elementwise LSTM update
        for (int e = tid; e < LROWS * HID; e += 512) {
            int r = e >> 7, k = e & 127;
            float ig = gs[r][k];
            float fg = gs[r][HID + k];
            float gg = gs[r][2 * HID + k];
            float og = gs[r][3 * HID + k];
            float c = sigf(fg) * c_s[r][k] + sigf(ig) * tanhf(gg);
            c_s[r][k] = c;
            h_s[r][k] = sigf(og) * tanhf(c);
        }
        __syncthreads();

        // fused heads: logits (6) + value (1)
        if (tid < LROWS * (NA + 1)) {
            int r = tid / (NA + 1);
            int col = tid % (NA + 1);
            float s;
            if (col < NA) {
                s = ba[col];
                for (int k = 0; k < HID; k++) s += h_s[r][k] * Wa[k * NA + col];
            } else {
                s = bc[0];
                for (int k = 0; k < HID; k++) s += h_s[r][k] * Wc[k];
            }
            out[((long long)t * B_ENV + r0 + r) * (NA + 1) + col] = s;
        }
        __syncthreads();
    }
}

// ---------------------------------------------------------------------------
// Launch
// ---------------------------------------------------------------------------
extern "C" void kernel_launch(void* const* d_in, const int* in_sizes, int n_in,
                              void* d_out, int out_size)
{
    const float* image = (const float*)d_in[0];
    const float* location = (const float*)d_in[1];
    const float* energy = (const float*)d_in[2];
    const int*   done  = (const int*)d_in[3];
    const float* h0 = (const float*)d_in[4];
    const float* c0 = (const float*)d_in[5];
    const float* W1 = (const float*)d_in[6];
    const float* b1 = (const float*)d_in[7];
    const float* W2 = (const float*)d_in[8];
    const float* b2 = (const float*)d_in[9];
    const float* W3 = (const float*)d_in[10];
    const float* b3 = (const float*)d_in[11];
    const float* W4 = (const float*)d_in[12];
    const float* b4 = (const float*)d_in[13];
    const float* Wl = (const float*)d_in[14];
    const float* bl = (const float*)d_in[15];
    const float* We = (const float*)d_in[16];
    const float* be = (const float*)d_in[17];
    const float* Wih = (const float*)d_in[18];
    const float* Whh = (const float*)d_in[19];
    const float* bih = (const float*)d_in[20];
    const float* bhh = (const float*)d_in[21];
    const float* Wa = (const float*)d_in[22];
    const float* ba = (const float*)d_in[23];
    const float* Wc = (const float*)d_in[24];
    const float* bc = (const float*)d_in[25];
    float* out = (float*)d_out;

    float *pb0, *pb1, *pfeat, *pgx;
    cudaGetSymbolAddress((void**)&pb0, g_b0);
    cudaGetSymbolAddress((void**)&pb1, g_b1);
    cudaGetSymbolAddress((void**)&pfeat, g_feat);
    cudaGetSymbolAddress((void**)&pgx, g_gx);

    const int M = N_TOT;
    dim3 blk(256);

    // L1: [N,25] @ W1[25,256] -> relu -> b0
    gemm_bias_kernel<false, true><<<dim3(M / 128, 2), blk>>>(
        image, W1, b1, nullptr, pb0, M, 256, 25, 1.f / 255.f, 256, 0);
    // L2: [N,256] @ W2[256,256] -> relu -> b1
    gemm_bias_kernel<false, true><<<dim3(M / 128, 2), blk>>>(
        pb0, W2, b2, nullptr, pb1, M, 256, 256, 1.f, 256, 0);
    // L3: [N,256] @ W3[256,128] -> relu -> b0 (ldc=128)
    gemm_bias_kernel<false, true><<<dim3(M / 128, 1), blk>>>(
        pb1, W3, b3, nullptr, pb0, M, 128, 256, 1.f, 128, 0);
    // L4: [N,128] @ W4[128,32] -> relu -> feats[:, 0:32]
    gemm_bias_kernel<false, true><<<dim3(M / 128, 1), blk>>>(
        pb0, W4, b4, nullptr, pfeat, M, 32, 128, 1.f, 96, 0);
    // loc / energy encoders -> feats[:, 32:96]
    smallenc_kernel<<<(N_TOT * 64 + 255) / 256, 256>>>(
        location, energy, Wl, bl, We, be, pfeat);
    // gx: [N,96] @ Wih^T[96,512] + bih + bhh
    gemm_bias_kernel<true, false><<<dim3(M / 128, 4), blk>>>(
        pfeat, Wih, bih, bhh, pgx, M, 512, 96, 1.f, 512, 0);
    // LSTM recurrence + fused heads
    lstm_kernel<<<B_ENV / LROWS, 512>>>(
        pgx, done, h0, c0, Whh, Wa, ba, Wc, bc, out);
}